// round 4
// baseline (speedup 1.0000x reference)
#include <cuda_runtime.h>
#include <cstdint>

// PhysicsAttention: N=64, C=128, T=256, V=25, O=128
// Round 4: mma.sync bf16 (3-pass hi/lo split) projections -> fp32 scratch; SIMT attention tail.
// (tcgen05 unavailable: harness PTX target is sm_100 without the 'a' feature suffix.)

#define NT_TOTAL 16384

// ---------------- device globals ----------------
// B-fragment-ordered weight images: 4 images (Mhi, Mlo, Vhi, Vlo), each 8192 uint32 (32KB).
// uint32 index within image: ((ntile*8 + kstep)*32 + lane)*2 + reg
__device__ uint32_t g_Bfrag[32768];
__device__ float g_u[128];
__device__ float g_bias[25 * 26];
__device__ float g_G[52428800];  // [row = tile*25+v][c]
__device__ float g_V[52428800];  // [row][o]

// ---------------- helpers ----------------
__device__ __forceinline__ unsigned short f2bf(float f) {
    unsigned short u;
    asm("cvt.rn.bf16.f32 %0, %1;" : "=h"(u) : "f"(f));
    return u;
}
__device__ __forceinline__ float bf2f(unsigned short u) {
    return __uint_as_float(((uint32_t)u) << 16);
}
__device__ __forceinline__ unsigned long long pk2(float a, float b) {
    unsigned long long r;
    asm("mov.b64 %0, {%1, %2};" : "=l"(r) : "f"(a), "f"(b));
    return r;
}
__device__ __forceinline__ void upk2(unsigned long long x, float& a, float& b) {
    asm("mov.b64 {%0, %1}, %2;" : "=f"(a), "=f"(b) : "l"(x));
}
__device__ __forceinline__ unsigned long long fma2(unsigned long long a,
                                                   unsigned long long b,
                                                   unsigned long long c) {
    unsigned long long d;
    asm("fma.rn.f32x2 %0, %1, %2, %3;" : "=l"(d) : "l"(a), "l"(b), "l"(c));
    return d;
}

// mma.sync m16n8k16 bf16 -> f32 accumulate (sm_80+, valid on compute_100 target)
#define MMA_BF16(d, a, b0v, b1v)                                                  \
    asm("mma.sync.aligned.m16n8k16.row.col.f32.bf16.bf16.f32 "                    \
        "{%0,%1,%2,%3},{%4,%5,%6,%7},{%8,%9},{%0,%1,%2,%3};"                      \
        : "+f"((d)[0]), "+f"((d)[1]), "+f"((d)[2]), "+f"((d)[3])                  \
        : "r"((a)[0]), "r"((a)[1]), "r"((a)[2]), "r"((a)[3]), "r"(b0v), "r"(b1v))

// A-image smem layout: [row][kp] with XOR swizzle.
// Conflict-free for row-major conversion writes AND mma fragment reads (verified):
//   swz(row) = ((row&15)<<2) | ((row>>3)&3);  idx = row*64 + (kp ^ swz)
__device__ __forceinline__ int aidx(int row, int kp) {
    return row * 64 + (kp ^ (((row & 15) << 2) | ((row >> 3) & 3)));
}

// ---------------- precompute: frag-ordered weight images, u, bias ----------------
__global__ void precompute_kernel(const float* __restrict__ wq,
                                  const float* __restrict__ bq,
                                  const float* __restrict__ wk,
                                  const float* __restrict__ wv,
                                  const float* __restrict__ bias_emb,
                                  const int* __restrict__ hop) {
    const float inv = 0.088388347648318447f;  // 1/sqrt(128)
    int b = blockIdx.x, k = threadIdx.x;
    if (b < 128) {
        const int n = b;
        // Bm[n][k] = M[k][n] = sum_o wq[o][k]*wk[o][n] * inv     (coalesced over k)
        float m = 0.f;
#pragma unroll 8
        for (int o = 0; o < 128; o++) m += wq[o * 128 + k] * wk[o * 128 + n];
        m *= inv;
        float wvv = wv[n * 128 + k];  // Bv[n][k] = wv[n][k]

        // fragment position of element (n, k) for mma m16n8k16 B (col) operand
        const int nt = n >> 3, j = n & 7, i = k & 15, ks = k >> 4;
        const int lane = j * 4 + ((i & 7) >> 1);
        const int reg = i >> 3;
        const int half = i & 1;
        const int u32idx = ((nt * 8 + ks) * 32 + lane) * 2 + reg;
        unsigned short* B16 = (unsigned short*)g_Bfrag;

        unsigned short mh = f2bf(m);
        unsigned short vh = f2bf(wvv);
        B16[(0 * 8192 + u32idx) * 2 + half] = mh;                 // Mhi
        B16[(1 * 8192 + u32idx) * 2 + half] = f2bf(m - bf2f(mh)); // Mlo
        B16[(2 * 8192 + u32idx) * 2 + half] = vh;                 // Vhi
        B16[(3 * 8192 + u32idx) * 2 + half] = f2bf(wvv - bf2f(vh)); // Vlo
    } else if (b == 128) {
        float uu = 0.f;
#pragma unroll 8
        for (int o = 0; o < 128; o++) uu += bq[o] * wk[o * 128 + k];
        g_u[k] = uu * inv;
    } else {
        for (int i = k; i < 625; i += 128) {
            int v = i / 25, w = i - v * 25;
            g_bias[v * 26 + w] = bias_emb[hop[i]];
        }
    }
}

// ---------------- proj kernel: G = X*M, V = X*wv^T via mma.sync ----------------
// 128 threads (4 warps), M = 128 rows/CTA (rows = tile*25+v globally, 409600 total, grid 3200).
// smem: B images 128KB (uint32[32768]) + A hi 32KB + A lo 32KB = 192KB dynamic.
extern __shared__ uint32_t sm_u32[];

__global__ __launch_bounds__(128, 1) void proj_kernel(const float* __restrict__ x) {
    uint32_t* Bs = sm_u32;            // 4 images x 8192
    uint32_t* Ahi = sm_u32 + 32768;   // 8192
    uint32_t* Alo = sm_u32 + 40960;   // 8192

    const int tid = threadIdx.x;
    const int lane = tid & 31;
    const int w = tid >> 5;

    // ---- phase 1a: convert this thread's row of x into bf16 hi/lo A images ----
    {
        const long R = (long)blockIdx.x * 128 + tid;     // global row = tile*25 + v
        const int nn = (int)(R / 6400);                  // batch index
        // x[n][c][t][v] flat addr = R + nn*812800 + k*6400
        const float* xrow = x + R + (long)nn * 812800;
#pragma unroll 4
        for (int kp = 0; kp < 64; kp++) {
            float x0 = xrow[(long)kp * 12800];
            float x1 = xrow[(long)kp * 12800 + 6400];
            unsigned short h0 = f2bf(x0), h1 = f2bf(x1);
            float l0 = x0 - bf2f(h0), l1 = x1 - bf2f(h1);
            int sidx = aidx(tid, kp);
            Ahi[sidx] = (uint32_t)h0 | ((uint32_t)h1 << 16);
            Alo[sidx] = (uint32_t)f2bf(l0) | ((uint32_t)f2bf(l1) << 16);
        }
    }
    // ---- phase 1b: copy weight images to smem ----
    {
        const uint4* src = (const uint4*)g_Bfrag;
        uint4* dst = (uint4*)Bs;
#pragma unroll 8
        for (int i = tid; i < 8192; i += 128) dst[i] = src[i];
    }
    __syncthreads();

    // ---- phase 2: MMA. warp w owns m-tiles 2w, 2w+1 ----
    const int g = lane >> 2, tc = lane & 3;
    float acc[2][16][4];

#pragma unroll 1
    for (int out = 0; out < 2; out++) {
#pragma unroll
        for (int m = 0; m < 2; m++)
#pragma unroll
            for (int nt = 0; nt < 16; nt++)
#pragma unroll
                for (int q = 0; q < 4; q++) acc[m][nt][q] = 0.f;

        const uint32_t* Bhi = Bs + out * 16384;  // out0: Mhi@0, out1: Vhi@16384
        const uint32_t* Blo = Bhi + 8192;

#pragma unroll 1
        for (int ks = 0; ks < 8; ks++) {
            uint32_t ah[2][4], al[2][4];
#pragma unroll
            for (int m = 0; m < 2; m++) {
                const int row0 = (2 * w + m) * 16 + g;
                const int kp0 = ks * 8 + tc;
                ah[m][0] = Ahi[aidx(row0, kp0)];
                ah[m][1] = Ahi[aidx(row0 + 8, kp0)];
                ah[m][2] = Ahi[aidx(row0, kp0 + 4)];
                ah[m][3] = Ahi[aidx(row0 + 8, kp0 + 4)];
                al[m][0] = Alo[aidx(row0, kp0)];
                al[m][1] = Alo[aidx(row0 + 8, kp0)];
                al[m][2] = Alo[aidx(row0, kp0 + 4)];
                al[m][3] = Alo[aidx(row0 + 8, kp0 + 4)];
            }
#pragma unroll
            for (int nt = 0; nt < 16; nt++) {
                const uint2 bh = ((const uint2*)Bhi)[(nt * 8 + ks) * 32 + lane];
                const uint2 bl = ((const uint2*)Blo)[(nt * 8 + ks) * 32 + lane];
#pragma unroll
                for (int m = 0; m < 2; m++) {
                    MMA_BF16(acc[m][nt], ah[m], bh.x, bh.y);  // hi*hi
                    MMA_BF16(acc[m][nt], ah[m], bl.x, bl.y);  // hi*lo
                    MMA_BF16(acc[m][nt], al[m], bh.x, bh.y);  // lo*hi
                }
            }
        }

        // ---- epilogue: fragment -> scratch ----
        float* dst = out ? g_V : g_G;
#pragma unroll
        for (int m = 0; m < 2; m++) {
            const long R0 = (long)blockIdx.x * 128 + (2 * w + m) * 16 + g;
#pragma unroll
            for (int nt = 0; nt < 16; nt++) {
                float2 s0 = make_float2(acc[m][nt][0], acc[m][nt][1]);
                float2 s1 = make_float2(acc[m][nt][2], acc[m][nt][3]);
                *(float2*)(dst + R0 * 128 + nt * 8 + tc * 2) = s0;
                *(float2*)(dst + (R0 + 8) * 128 + nt * 8 + tc * 2) = s1;
            }
        }
    }
}

// ---------------- attn kernel: S = G.x (+bias), softmax, attn.V, store ----------------
__global__ __launch_bounds__(256) void attn_kernel(const float* __restrict__ x,
                                                   const float* __restrict__ bv,
                                                   float* __restrict__ out) {
    __shared__ float xs[128 * 26];  // x[c][v], col 25 zero-padded
    __shared__ float Gs[25 * 132];  // G'[v][c'] (reused as outs stride 129)
    __shared__ float Vs[25 * 128];  // V[v][o]
    __shared__ float sc[25 * 26];
    __shared__ float at[25 * 26];

    const int tid = threadIdx.x;
    const int tile = blockIdx.x;
    const int n = tile >> 8;
    const int t = tile & 255;
    const long xbase = (long)n * 819200 + (long)t * 25;
    const long gbase = (long)tile * 3200;

    for (int idx = tid; idx < 3200; idx += 256) {
        int c = idx / 25;
        int v = idx - c * 25;
        xs[c * 26 + v] = x[xbase + (long)c * 6400 + v];
    }
    for (int c = tid; c < 128; c += 256) xs[c * 26 + 25] = 0.f;
    for (int idx = tid; idx < 3200; idx += 256) {
        int v = idx >> 7, c = idx & 127;
        Gs[v * 132 + c] = g_G[gbase + idx] + g_u[c];
    }
    for (int idx = tid; idx < 3200; idx += 256) {
        int v = idx >> 7, o = idx & 127;
        Vs[v * 128 + o] = g_V[gbase + idx] + bv[o];
    }
    __syncthreads();

    // S[v][w] = sum_c G'[v][c] * x[c][w] + bias
    for (int W = tid; W < 325; W += 256) {
        int wp = W / 25;
        int v = W - wp * 25;
        unsigned long long acc = 0ULL;
        const float* gr = Gs + v * 132;
#pragma unroll 4
        for (int c4 = 0; c4 < 128; c4 += 4) {
            float4 g4 = *(const float4*)(gr + c4);
            acc = fma2(pk2(g4.x, g4.x),
                       *(const unsigned long long*)(xs + (c4 + 0) * 26 + 2 * wp), acc);
            acc = fma2(pk2(g4.y, g4.y),
                       *(const unsigned long long*)(xs + (c4 + 1) * 26 + 2 * wp), acc);
            acc = fma2(pk2(g4.z, g4.z),
                       *(const unsigned long long*)(xs + (c4 + 2) * 26 + 2 * wp), acc);
            acc = fma2(pk2(g4.w, g4.w),
                       *(const unsigned long long*)(xs + (c4 + 3) * 26 + 2 * wp), acc);
        }
        float s0, s1;
        upk2(acc, s0, s1);
        int w0 = 2 * wp;
        sc[v * 26 + w0] = s0 + g_bias[v * 26 + w0];
        if (w0 + 1 < 25) sc[v * 26 + w0 + 1] = s1 + g_bias[v * 26 + w0 + 1];
    }
    __syncthreads();

    // softmax rows, store transposed attn^T[w][v]
    {
        int lane = tid & 31, wid = tid >> 5;
        for (int v = wid; v < 25; v += 8) {
            float sv = (lane < 25) ? sc[v * 26 + lane] : -1e30f;
            float m = sv;
#pragma unroll
            for (int d = 16; d; d >>= 1) m = fmaxf(m, __shfl_xor_sync(0xffffffffu, m, d));
            float e = (lane < 25) ? __expf(sv - m) : 0.f;
            float s = e;
#pragma unroll
            for (int d = 16; d; d >>= 1) s += __shfl_xor_sync(0xffffffffu, s, d);
            float a = e * __fdividef(1.f, s);
            if (lane < 25) at[lane * 26 + v] = a;
        }
    }
    __syncthreads();

    // out[v][o] = sum_w attn[v][w] * V[w][o]
    const int o = tid & 127;
    const int g = tid >> 7;
    const int pbase = g * 6;
    unsigned long long accO[7];
#pragma unroll
    for (int p = 0; p < 7; p++) accO[p] = 0ULL;
#pragma unroll 1
    for (int w = 0; w < 25; w++) {
        float vv = Vs[w * 128 + o];
        unsigned long long vv2 = pk2(vv, vv);
        const unsigned long long* ar = (const unsigned long long*)(at + w * 26) + pbase;
#pragma unroll
        for (int p = 0; p < 7; p++) accO[p] = fma2(ar[p], vv2, accO[p]);
    }

    float* outs = Gs;  // reuse, stride 129
#pragma unroll
    for (int p = 0; p < 7; p++) {
        int v0 = 2 * (pbase + p);
        float a, b;
        upk2(accO[p], a, b);
        outs[v0 * 129 + o] = a;
        if (v0 + 1 < 25) outs[(v0 + 1) * 129 + o] = b;
    }
    __syncthreads();

    const long obase = (long)n * 819200 + (long)t * 25;
    for (int idx = tid; idx < 3200; idx += 256) {
        int oo = idx / 25;
        int v = idx - oo * 25;
        out[obase + (long)oo * 6400 + v] = outs[v * 129 + oo];
    }
}

extern "C" void kernel_launch(void* const* d_in, const int* in_sizes, int n_in,
                              void* d_out, int out_size) {
    (void)in_sizes; (void)n_in; (void)out_size;
    const float* x = (const float*)d_in[0];
    const float* wq = (const float*)d_in[1];
    const float* bq = (const float*)d_in[2];
    const float* wk = (const float*)d_in[3];
    // d_in[4] = bk: softmax-invariant (row-constant), unused
    const float* wv = (const float*)d_in[5];
    const float* bv = (const float*)d_in[6];
    const float* be = (const float*)d_in[7];
    const int* hop = (const int*)d_in[8];

    static int smem_set = 0;
    if (!smem_set) {
        cudaFuncSetAttribute(proj_kernel, cudaFuncAttributeMaxDynamicSharedMemorySize,
                             196608);
        smem_set = 1;
    }

    precompute_kernel<<<130, 128>>>(wq, bq, wk, wv, be, hop);
    proj_kernel<<<3200, 128, 196608>>>(x);
    attn_kernel<<<NT_TOTAL, 256>>>(x, bv, (float*)d_out);
}

// round 7
// speedup vs baseline: 1.2116x; 1.2116x over previous
#include <cuda_runtime.h>
#include <cstdint>

// PhysicsAttention: N=64, C=128, T=256, V=25, O=128
// Round 7 = Round 5 design (two infra failures, never measured), static guard removed:
//   proj = mma.sync bf16 3-pass split, pass-major (8 warps/CTA);
//   attn = quad-w S-phase + float4 loads.

#define NT_TOTAL 16384

// ---------------- device globals ----------------
// B-fragment-ordered weight images: 4 images (Mhi, Mlo, Vhi, Vlo), each 8192 uint32 (32KB).
// uint32 index within image: ((ntile*8 + kstep)*32 + lane)*2 + reg
__device__ uint32_t g_Bfrag[32768];
__device__ float g_u[128];
__device__ float g_bias[25 * 26];
__device__ float g_G[52428800];  // [row = tile*25+v][c]
__device__ float g_V[52428800];  // [row][o]

// ---------------- helpers ----------------
__device__ __forceinline__ unsigned short f2bf(float f) {
    unsigned short u;
    asm("cvt.rn.bf16.f32 %0, %1;" : "=h"(u) : "f"(f));
    return u;
}
__device__ __forceinline__ float bf2f(unsigned short u) {
    return __uint_as_float(((uint32_t)u) << 16);
}
__device__ __forceinline__ unsigned long long pk2(float a, float b) {
    unsigned long long r;
    asm("mov.b64 %0, {%1, %2};" : "=l"(r) : "f"(a), "f"(b));
    return r;
}
__device__ __forceinline__ void upk2(unsigned long long x, float& a, float& b) {
    asm("mov.b64 {%0, %1}, %2;" : "=f"(a), "=f"(b) : "l"(x));
}
__device__ __forceinline__ unsigned long long fma2(unsigned long long a,
                                                   unsigned long long b,
                                                   unsigned long long c) {
    unsigned long long d;
    asm("fma.rn.f32x2 %0, %1, %2, %3;" : "=l"(d) : "l"(a), "l"(b), "l"(c));
    return d;
}

// mma.sync m16n8k16 bf16 -> f32 accumulate (sm_80+, valid on compute_100 target)
#define MMA_BF16(d, a, b0v, b1v)                                                  \
    asm("mma.sync.aligned.m16n8k16.row.col.f32.bf16.bf16.f32 "                    \
        "{%0,%1,%2,%3},{%4,%5,%6,%7},{%8,%9},{%0,%1,%2,%3};"                      \
        : "+f"((d)[0]), "+f"((d)[1]), "+f"((d)[2]), "+f"((d)[3])                  \
        : "r"((a)[0]), "r"((a)[1]), "r"((a)[2]), "r"((a)[3]), "r"(b0v), "r"(b1v))

// A-image smem layout: [row][kp] with XOR swizzle (conflict-free for
// row-major conversion writes AND fragment reads):
__device__ __forceinline__ int aidx(int row, int kp) {
    return row * 64 + (kp ^ (((row & 15) << 2) | ((row >> 3) & 3)));
}

// ---------------- precompute: frag-ordered weight images, u, bias ----------------
__global__ void precompute_kernel(const float* __restrict__ wq,
                                  const float* __restrict__ bq,
                                  const float* __restrict__ wk,
                                  const float* __restrict__ wv,
                                  const float* __restrict__ bias_emb,
                                  const int* __restrict__ hop) {
    const float inv = 0.088388347648318447f;  // 1/sqrt(128)
    int b = blockIdx.x, k = threadIdx.x;
    if (b < 128) {
        const int n = b;
        float m = 0.f;
#pragma unroll 8
        for (int o = 0; o < 128; o++) m += wq[o * 128 + k] * wk[o * 128 + n];
        m *= inv;
        float wvv = wv[n * 128 + k];

        // fragment position of element (n, k) for mma m16n8k16 B (col) operand
        const int nt = n >> 3, j = n & 7, i = k & 15, ks = k >> 4;
        const int lane = j * 4 + ((i & 7) >> 1);
        const int reg = i >> 3;
        const int half = i & 1;
        const int u32idx = ((nt * 8 + ks) * 32 + lane) * 2 + reg;
        unsigned short* B16 = (unsigned short*)g_Bfrag;

        unsigned short mh = f2bf(m);
        unsigned short vh = f2bf(wvv);
        B16[(0 * 8192 + u32idx) * 2 + half] = mh;                   // Mhi
        B16[(1 * 8192 + u32idx) * 2 + half] = f2bf(m - bf2f(mh));   // Mlo
        B16[(2 * 8192 + u32idx) * 2 + half] = vh;                   // Vhi
        B16[(3 * 8192 + u32idx) * 2 + half] = f2bf(wvv - bf2f(vh)); // Vlo
    } else if (b == 128) {
        float uu = 0.f;
#pragma unroll 8
        for (int o = 0; o < 128; o++) uu += bq[o] * wk[o * 128 + k];
        g_u[k] = uu * inv;
    } else {
        for (int i = k; i < 625; i += 128) {
            int v = i / 25, w = i - v * 25;
            g_bias[v * 26 + w] = bias_emb[hop[i]];
        }
    }
}

// ---------------- proj kernel: G = X*M, V = X*wv^T via mma.sync ----------------
// 256 threads (8 warps), 128 rows/CTA (row = tile*25+v globally, 409600 total, grid 3200).
// smem: B images 128KB + A hi 32KB + A lo 32KB = 192KB dynamic. Warp w owns m-tile w.
extern __shared__ uint32_t sm_u32[];

__global__ __launch_bounds__(256, 1) void proj_kernel(const float* __restrict__ x) {
    uint32_t* Bs = sm_u32;            // 4 images x 8192
    uint32_t* Ahi = sm_u32 + 32768;   // 8192
    uint32_t* Alo = sm_u32 + 40960;   // 8192

    const int tid = threadIdx.x;
    const int lane = tid & 31;
    const int w = tid >> 5;

    // ---- phase 1a: convert x rows into bf16 hi/lo A images (2 threads/row) ----
    {
        const int row = tid & 127;
        const int half = tid >> 7;  // kp 32-range selector
        const long R = (long)blockIdx.x * 128 + row;  // global row = tile*25 + v
        const int nn = (int)(R / 6400);
        const float* xrow = x + R + (long)nn * 812800;
#pragma unroll 4
        for (int j = 0; j < 32; j++) {
            const int kp = half * 32 + j;
            float x0 = xrow[(long)kp * 12800];
            float x1 = xrow[(long)kp * 12800 + 6400];
            unsigned short h0 = f2bf(x0), h1 = f2bf(x1);
            float l0 = x0 - bf2f(h0), l1 = x1 - bf2f(h1);
            int sidx = aidx(row, kp);
            Ahi[sidx] = (uint32_t)h0 | ((uint32_t)h1 << 16);
            Alo[sidx] = (uint32_t)f2bf(l0) | ((uint32_t)f2bf(l1) << 16);
        }
    }
    // ---- phase 1b: copy weight images to smem ----
    {
        const uint4* src = (const uint4*)g_Bfrag;
        uint4* dst = (uint4*)Bs;
#pragma unroll 8
        for (int i = tid; i < 8192; i += 256) dst[i] = src[i];
    }
    __syncthreads();

    // ---- phase 2: MMA, pass-major (16 independent accumulators between revisits) ----
    const int g = lane >> 2, tc = lane & 3;

#pragma unroll 1
    for (int out = 0; out < 2; out++) {
        float acc[16][4];
#pragma unroll
        for (int nt = 0; nt < 16; nt++)
#pragma unroll
            for (int q = 0; q < 4; q++) acc[nt][q] = 0.f;

#pragma unroll 1
        for (int pass = 0; pass < 3; pass++) {
            const uint32_t* Aimg = (pass == 2) ? Alo : Ahi;
            const uint32_t* Bimg = Bs + out * 16384 + ((pass == 1) ? 8192 : 0);
#pragma unroll 1
            for (int ks = 0; ks < 8; ks++) {
                const int row0 = w * 16 + g;
                const int kp0 = ks * 8 + tc;
                uint32_t a[4];
                a[0] = Aimg[aidx(row0, kp0)];
                a[1] = Aimg[aidx(row0 + 8, kp0)];
                a[2] = Aimg[aidx(row0, kp0 + 4)];
                a[3] = Aimg[aidx(row0 + 8, kp0 + 4)];
#pragma unroll
                for (int nt = 0; nt < 16; nt++) {
                    const uint2 b = ((const uint2*)Bimg)[(nt * 8 + ks) * 32 + lane];
                    MMA_BF16(acc[nt], a, b.x, b.y);
                }
            }
        }

        // ---- epilogue: fragment -> scratch (row-major fp32) ----
        float* dst = out ? g_V : g_G;
        const long R0 = (long)blockIdx.x * 128 + w * 16 + g;
#pragma unroll
        for (int nt = 0; nt < 16; nt++) {
            *(float2*)(dst + R0 * 128 + nt * 8 + tc * 2) =
                make_float2(acc[nt][0], acc[nt][1]);
            *(float2*)(dst + (R0 + 8) * 128 + nt * 8 + tc * 2) =
                make_float2(acc[nt][2], acc[nt][3]);
        }
    }
}

// ---------------- attn kernel: S = G.x (+bias), softmax, attn.V, store ----------------
__global__ __launch_bounds__(256) void attn_kernel(const float* __restrict__ x,
                                                   const float* __restrict__ bv,
                                                   float* __restrict__ out) {
    __shared__ float xs[128 * 28];  // x[c][v], stride 28, cols 25-27 zeroed
    __shared__ float Gs[25 * 132];  // G'[v][c] (reused as outs stride 129)
    __shared__ float Vs[25 * 128];  // V[v][o]
    __shared__ float sc[25 * 26];
    __shared__ float at[25 * 28];   // attn^T[w][v], stride 28, cols 25-27 zeroed

    const int tid = threadIdx.x;
    const int tile = blockIdx.x;
    const int n = tile >> 8;
    const int t = tile & 255;
    const long xbase = (long)n * 819200 + (long)t * 25;
    const long gbase = (long)tile * 3200;

    // x tile (coalesced 25-float runs)
    for (int idx = tid; idx < 3200; idx += 256) {
        int c = idx / 25;
        int v = idx - c * 25;
        xs[c * 28 + v] = x[xbase + (long)c * 6400 + v];
    }
    for (int i = tid; i < 384; i += 256) {  // zero pad cols 25..27
        int c = i / 3, j = i - c * 3;
        xs[c * 28 + 25 + j] = 0.f;
    }
    if (tid < 75) {  // zero pad at cols 25..27
        int ww = tid / 3, j = tid - ww * 3;
        at[ww * 28 + 25 + j] = 0.f;
    }
    // G,V scratch: float4 loads (800 each)
    for (int i4 = tid; i4 < 800; i4 += 256) {
        int v = i4 >> 5;
        int c = (i4 & 31) * 4;
        float4 gv = *(const float4*)(g_G + gbase + v * 128 + c);
        float4 uu = *(const float4*)(g_u + c);
        gv.x += uu.x; gv.y += uu.y; gv.z += uu.z; gv.w += uu.w;
        *(float4*)(Gs + v * 132 + c) = gv;
        float4 vv = *(const float4*)(g_V + gbase + v * 128 + c);
        float4 bb = *(const float4*)(bv + c);
        vv.x += bb.x; vv.y += bb.y; vv.z += bb.z; vv.w += bb.w;
        *(float4*)(Vs + v * 128 + c) = vv;
    }
    __syncthreads();

    // ---- S quad-w: thread (v, wq) computes S[v][4wq..4wq+3] ----
    if (tid < 175) {
        const int v = tid / 7;
        const int wq = tid - v * 7;
        const int w0 = wq * 4;
        float s0 = 0.f, s1 = 0.f, s2 = 0.f, s3 = 0.f;
        const float* gr = Gs + v * 132;
        const float* xc = xs + w0;
#pragma unroll 8
        for (int c4 = 0; c4 < 128; c4 += 4) {
            float4 g4 = *(const float4*)(gr + c4);
            float4 xa = *(const float4*)(xc + (c4 + 0) * 28);
            float4 xb = *(const float4*)(xc + (c4 + 1) * 28);
            float4 xcv = *(const float4*)(xc + (c4 + 2) * 28);
            float4 xd = *(const float4*)(xc + (c4 + 3) * 28);
            s0 = fmaf(g4.x, xa.x, s0); s1 = fmaf(g4.x, xa.y, s1);
            s2 = fmaf(g4.x, xa.z, s2); s3 = fmaf(g4.x, xa.w, s3);
            s0 = fmaf(g4.y, xb.x, s0); s1 = fmaf(g4.y, xb.y, s1);
            s2 = fmaf(g4.y, xb.z, s2); s3 = fmaf(g4.y, xb.w, s3);
            s0 = fmaf(g4.z, xcv.x, s0); s1 = fmaf(g4.z, xcv.y, s1);
            s2 = fmaf(g4.z, xcv.z, s2); s3 = fmaf(g4.z, xcv.w, s3);
            s0 = fmaf(g4.w, xd.x, s0); s1 = fmaf(g4.w, xd.y, s1);
            s2 = fmaf(g4.w, xd.z, s2); s3 = fmaf(g4.w, xd.w, s3);
        }
        sc[v * 26 + w0] = s0 + g_bias[v * 26 + w0];
        if (w0 + 1 < 25) sc[v * 26 + w0 + 1] = s1 + g_bias[v * 26 + w0 + 1];
        if (w0 + 2 < 25) sc[v * 26 + w0 + 2] = s2 + g_bias[v * 26 + w0 + 2];
        if (w0 + 3 < 25) sc[v * 26 + w0 + 3] = s3 + g_bias[v * 26 + w0 + 3];
    }
    __syncthreads();

    // ---- softmax rows, store transposed attn^T[w][v] ----
    {
        int lane = tid & 31, wid = tid >> 5;
        for (int v = wid; v < 25; v += 8) {
            float sv = (lane < 25) ? sc[v * 26 + lane] : -1e30f;
            float m = sv;
#pragma unroll
            for (int d = 16; d; d >>= 1) m = fmaxf(m, __shfl_xor_sync(0xffffffffu, m, d));
            float e = (lane < 25) ? __expf(sv - m) : 0.f;
            float s = e;
#pragma unroll
            for (int d = 16; d; d >>= 1) s += __shfl_xor_sync(0xffffffffu, s, d);
            float a = e * __fdividef(1.f, s);
            if (lane < 25) at[lane * 28 + v] = a;
        }
    }
    __syncthreads();

    // ---- out[v][o] = sum_w attn[v][w] * V[w][o] ----
    const int o = tid & 127;
    const int g = tid >> 7;
    const int pbase = g * 6;
    unsigned long long accO[7];
#pragma unroll
    for (int p = 0; p < 7; p++) accO[p] = 0ULL;
#pragma unroll 1
    for (int w = 0; w < 25; w++) {
        float vv = Vs[w * 128 + o];
        unsigned long long vv2 = pk2(vv, vv);
        const unsigned long long* ar = (const unsigned long long*)(at + w * 28) + pbase;
#pragma unroll
        for (int p = 0; p < 7; p++) accO[p] = fma2(ar[p], vv2, accO[p]);
    }

    float* outs = Gs;  // reuse, stride 129
#pragma unroll
    for (int p = 0; p < 7; p++) {
        int v0 = 2 * (pbase + p);
        float a, b;
        upk2(accO[p], a, b);
        outs[v0 * 129 + o] = a;
        if (v0 + 1 < 25) outs[(v0 + 1) * 129 + o] = b;
    }
    __syncthreads();

    const long obase = (long)n * 819200 + (long)t * 25;
    for (int idx = tid; idx < 3200; idx += 256) {
        int oo = idx / 25;
        int v = idx - oo * 25;
        out[obase + (long)oo * 6400 + v] = outs[v * 129 + oo];
    }
}

extern "C" void kernel_launch(void* const* d_in, const int* in_sizes, int n_in,
                              void* d_out, int out_size) {
    (void)in_sizes; (void)n_in; (void)out_size;
    const float* x = (const float*)d_in[0];
    const float* wq = (const float*)d_in[1];
    const float* bq = (const float*)d_in[2];
    const float* wk = (const float*)d_in[3];
    // d_in[4] = bk: softmax-invariant (row-constant), unused
    const float* wv = (const float*)d_in[5];
    const float* bv = (const float*)d_in[6];
    const float* be = (const float*)d_in[7];
    const int* hop = (const int*)d_in[8];

    cudaFuncSetAttribute(proj_kernel, cudaFuncAttributeMaxDynamicSharedMemorySize,
                         196608);

    precompute_kernel<<<130, 128>>>(wq, bq, wk, wv, be, hop);
    proj_kernel<<<3200, 256, 196608>>>(x);
    attn_kernel<<<NT_TOTAL, 256>>>(x, bv, (float*)d_out);
}